// round 5
// baseline (speedup 1.0000x reference)
#include <cuda_runtime.h>
#include <cuda_fp16.h>

// CostVolumeManager: plane-sweep cost volume. B=1, S=8, C=16, H=64, W=96, D=64.
//
// v4 (latency-bound fix): two consecutive depth bins per thread.
//   - P·ray shared across both depths (projection linear in depth)
//   - geometric depths: depth1 = depth0 * exp(log-step)
//   - fully branchless taps: z>0 mask and OOB validity folded into weights,
//     gx/gy range-clamped so no Inf/NaN can reach the weight math, indices
//     clamped both directions -> no divergence, loads of both depths batched.
//   - consecutive depths hit adjacent source pixels -> tap L1 lines shared.

namespace cvk {

constexpr int S = 8, C = 16, H = 64, W = 96, D = 64, N = H * W;
constexpr int SRC_PACK_BLOCKS = (S * N * 4) / 256;   // 768
constexpr int CUR_PACK_BLOCKS = (N * 4) / 256;       // 96

typedef unsigned long long ull;

// Static device scratch (no allocation).
__device__ uint4  g_srcA[S * N];   // fp16 ch0..7  per pixel (4 x half2)
__device__ uint4  g_srcB[S * N];   // fp16 ch8..15 per pixel
__device__ float4 g_cur[4 * N];    // fp32 cur feats, plane q holds ch 4q..4q+3

// ---------------------------------------------------------------- pack pass
__global__ __launch_bounds__(256)
void pack_all(const float* __restrict__ src, const float* __restrict__ cur) {
    int bid = blockIdx.x;
    if (bid < SRC_PACK_BLOCKS) {
        int idx = bid * 256 + threadIdx.x;        // h*(S*N) + s*N + n
        int h = idx / (S * N);
        int sn = idx - h * (S * N);
        int n_local = sn % N;
        int s = sn / N;
        const float* p = src + (size_t)s * C * N + (size_t)(4 * h) * N + n_local;
        __half2 a = __floats2half2_rn(p[0],     p[N]);
        __half2 b = __floats2half2_rn(p[2 * N], p[3 * N]);
        uint2 v;
        v.x = *reinterpret_cast<unsigned*>(&a);
        v.y = *reinterpret_cast<unsigned*>(&b);
        uint2* plane = (h < 2) ? reinterpret_cast<uint2*>(g_srcA)
                               : reinterpret_cast<uint2*>(g_srcB);
        plane[(size_t)sn * 2 + (h & 1)] = v;
    } else {
        int idx = (bid - SRC_PACK_BLOCKS) * 256 + threadIdx.x;  // q*N + n
        int q = idx / N;
        int n = idx - q * N;
        float4 f;
        f.x = cur[(size_t)(4 * q + 0) * N + n];
        f.y = cur[(size_t)(4 * q + 1) * N + n];
        f.z = cur[(size_t)(4 * q + 2) * N + n];
        f.w = cur[(size_t)(4 * q + 3) * N + n];
        g_cur[idx] = f;
    }
}

// ------------------------------------------------------------ packed helpers
__device__ __forceinline__ ull pack_f2(float lo, float hi) {
    ull u;
    asm("mov.b64 %0, {%1, %2};" : "=l"(u) : "f"(lo), "f"(hi));
    return u;
}
__device__ __forceinline__ void unpack_f2(ull u, float& lo, float& hi) {
    asm("mov.b64 {%0, %1}, %2;" : "=f"(lo), "=f"(hi) : "l"(u));
}
__device__ __forceinline__ void fma_f32x2(ull& d, ull a, ull b) {
    asm("fma.rn.f32x2 %0, %1, %2, %3;" : "=l"(d) : "l"(a), "l"(b), "l"(d));
}

// Blend 4 taps (one 16B plane = 4 half2) with fp16 weights, dot against
// packed fp32 cur pairs, accumulating into acc (f32x2).
__device__ __forceinline__ void blend_dot(ull& acc,
                                          uint4 t00, uint4 t10, uint4 t01, uint4 t11,
                                          __half2 h00, __half2 h10,
                                          __half2 h01, __half2 h11,
                                          const ull* __restrict__ cfp) {
#pragma unroll
    for (int j = 0; j < 4; j++) {
        __half2 a = *(reinterpret_cast<__half2*>(&t00.x) + j);
        __half2 b = *(reinterpret_cast<__half2*>(&t10.x) + j);
        __half2 c = *(reinterpret_cast<__half2*>(&t01.x) + j);
        __half2 e = *(reinterpret_cast<__half2*>(&t11.x) + j);
        __half2 v = __hmul2(a, h00);
        v = __hfma2(b, h10, v);
        v = __hfma2(c, h01, v);
        v = __hfma2(e, h11, v);
        float2 f = __half22float2(v);
        fma_f32x2(acc, pack_f2(f.x, f.y), cfp[j]);
    }
}

// One depth bin through one source, branch-free.
__device__ __forceinline__ void proc_depth(ull& acc, float dep,
                                           float au, float av, float az,
                                           float bu, float bv, float bz,
                                           int sbase,
                                           const ull* __restrict__ cfp) {
    float pu = dep * au + bu;
    float pv = dep * av + bv;
    float pz = dep * az + bz;
    float iz = 1.f / (pz + 1e-8f);
    float gx = pu * iz - 0.5f;
    float gy = pv * iz - 0.5f;
    // Range clamp: keeps weight math finite for degenerate projections.
    // Any clamped coordinate lands with both taps OOB -> weights forced to 0.
    gx = fminf(fmaxf(gx, -2.f), (float)(W + 1));
    gy = fminf(fmaxf(gy, -2.f), (float)(H + 1));
    float x0f = floorf(gx), y0f = floorf(gy);
    float wx = gx - x0f, wy = gy - y0f;
    int x0 = (int)x0f, y0 = (int)y0f;

    float zm  = (pz > 0.f) ? 1.f : 0.f;                      // mask = z > 0
    float wx0 = (x0 >= 0  && x0 < W)     ? (1.f - wx) : 0.f; // tap validity
    float wx1 = (x0 >= -1 && x0 < W - 1) ? wx         : 0.f;
    float wy0 = (y0 >= 0  && y0 < H)     ? zm * (1.f - wy) : 0.f;
    float wy1 = (y0 >= -1 && y0 < H - 1) ? zm * wy         : 0.f;
    __half2 h00 = __float2half2_rn(wx0 * wy0);
    __half2 h10 = __float2half2_rn(wx1 * wy0);
    __half2 h01 = __float2half2_rn(wx0 * wy1);
    __half2 h11 = __float2half2_rn(wx1 * wy1);

    int xc0 = min(max(x0, 0),     W - 1);
    int xc1 = min(max(x0 + 1, 0), W - 1);
    int yc0 = min(max(y0, 0),     H - 1);
    int yc1 = min(max(y0 + 1, 0), H - 1);
    int i00 = sbase + yc0 * W + xc0;
    int i10 = sbase + yc0 * W + xc1;
    int i01 = sbase + yc1 * W + xc0;
    int i11 = sbase + yc1 * W + xc1;

    uint4 a00 = g_srcA[i00], a10 = g_srcA[i10];
    uint4 a01 = g_srcA[i01], a11 = g_srcA[i11];
    uint4 b00 = g_srcB[i00], b10 = g_srcB[i10];
    uint4 b01 = g_srcB[i01], b11 = g_srcB[i11];

    blend_dot(acc, a00, a10, a01, a11, h00, h10, h01, h11, cfp + 0);
    blend_dot(acc, b00, b10, b01, b11, h00, h10, h01, h11, cfp + 4);
}

// --------------------------------------------------------------- main kernel
__global__ __launch_bounds__(128)
void cost_main(const float* __restrict__ exts, const float* __restrict__ Ks,
               const float* __restrict__ invK, const float* __restrict__ mnp,
               const float* __restrict__ mxp, float* __restrict__ out) {
    __shared__ float sP[S][12];
    int t = threadIdx.y * 32 + threadIdx.x;
    if (t < S * 12) {
        int s = t / 12, rc = t - 12 * s, r = rc >> 2, c = rc & 3;
        float accm = 0.f;
#pragma unroll
        for (int k = 0; k < 4; k++)
            accm += Ks[s * 16 + r * 4 + k] * exts[s * 16 + k * 4 + c];
        sP[s][rc] = accm;
    }
    __syncthreads();

    int x = blockIdx.x * 32 + threadIdx.x;
    int y = blockIdx.y;
    int d0 = (blockIdx.z * 4 + threadIdx.y) * 2;   // this thread: d0, d0+1
    int n = y * W + x;

    // Geometric depth bins: dep1 = dep0 * exp(step)
    float mnv = mnp[0], mxv = mxp[0];
    float lstep = logf(mxv / mnv) * (1.f / 63.f);
    float dep0 = expf(logf(mnv) + lstep * (float)d0);
    float dep1 = dep0 * expf(lstep);

    // Unit-depth back-projected ray (depth folded in per-source via linearity)
    float pxc = (float)x + 0.5f, pyc = (float)y + 0.5f;
    float rx = invK[0] * pxc + invK[1] * pyc + invK[2];
    float ry = invK[4] * pxc + invK[5] * pyc + invK[6];
    float rz = invK[8] * pxc + invK[9] * pyc + invK[10];

    // Current-frame features as 8 packed f32x2 pairs (shared by both depths).
    ull cfp[8];
#pragma unroll
    for (int q = 0; q < 4; q++) {
        float4 f = g_cur[q * N + n];
        cfp[2 * q + 0] = pack_f2(f.x, f.y);
        cfp[2 * q + 1] = pack_f2(f.z, f.w);
    }

    ull acc0 = 0ull, acc1 = 0ull;

#pragma unroll
    for (int s = 0; s < S; s++) {
        const float* P = sP[s];
        float au = P[0] * rx + P[1] * ry + P[2]  * rz;
        float av = P[4] * rx + P[5] * ry + P[6]  * rz;
        float az = P[8] * rx + P[9] * ry + P[10] * rz;
        float bu = P[3], bv = P[7], bz = P[11];
        int sbase = s * N;
        proc_depth(acc0, dep0, au, av, az, bu, bv, bz, sbase, cfp);
        proc_depth(acc1, dep1, au, av, az, bu, bv, bz, sbase, cfp);
    }

    float lo, hi;
    unpack_f2(acc0, lo, hi);
    out[d0 * N + n] = lo + hi;                 // cost_volume
    unpack_f2(acc1, lo, hi);
    out[(d0 + 1) * N + n] = lo + hi;
    out[D * N + d0 * N + n] = dep0;            // depth_planes
    out[D * N + (d0 + 1) * N + n] = dep1;
}

}  // namespace cvk

extern "C" void kernel_launch(void* const* d_in, const int* in_sizes, int n_in,
                              void* d_out, int out_size) {
    using namespace cvk;
    const float* cur  = (const float*)d_in[0];  // [1,16,64,96]
    const float* src  = (const float*)d_in[1];  // [1,8,16,64,96]
    const float* exts = (const float*)d_in[2];  // [1,8,4,4]
    const float* Ks   = (const float*)d_in[3];  // [1,8,4,4]
    const float* invK = (const float*)d_in[4];  // [1,4,4]
    const float* mnp  = (const float*)d_in[5];  // [1,1,1,1]
    const float* mxp  = (const float*)d_in[6];  // [1,1,1,1]
    float* out = (float*)d_out;

    pack_all<<<SRC_PACK_BLOCKS + CUR_PACK_BLOCKS, 256>>>(src, cur);

    dim3 blk(32, 4);
    dim3 grd(W / 32, H, D / 8);   // 2 depths per thread, 8 depths per block
    cost_main<<<grd, blk>>>(exts, Ks, invK, mnp, mxp, out);
}